// round 10
// baseline (speedup 1.0000x reference)
#include <cuda_runtime.h>

// CostVolumeBlock: horizontal correlation cost volume.
// c1, warp: [B=8, H=192, W=640, C=32] float32 (NHWC).
// out: [B, H, W, 37] = 32 c1 passthrough channels + 5 disparity costs
//      cost[o] = mean_c( c1[b,h,w,c] * warp[b,h,w+o-2,c] ), zero outside [0,W).
//
// R8/R9: A/B experiment in one bench (GPU rounds are scarce — measure both
// store strategies in a single hold).
//   Kernel A (pixels [0, N/2)):  smem-staged writeback -> 296 coalesced
//                                STG.128 per block (R3 store path).
//   Kernel B (pixels [N/2, N)):  direct stores, 4x STG.32 sweeps + predicated
//                                cost STG (R2 store path).
// Both share identical front-batched clamped loads + multiplicative edge
// masks, isolating the store variable in the per-launch metrics.

namespace {
constexpr int kW = 640;
constexpr int kC = 32;
constexpr int kSR = 2;
constexpr int kOff = 2 * kSR + 1;            // 5
constexpr int kOutC = kC + kOff;             // 37
constexpr int kPixels = 8 * 192 * 640;       // 983040
constexpr int kHalfPixels = kPixels / 2;     // 491520
constexpr int kPixPerWarp = 4;
constexpr int kThreads = 256;                // 8 warps
constexpr int kPixPerBlock = (kThreads / 32) * kPixPerWarp;     // 32
constexpr int kSmemFloats = kPixPerBlock * kOutC;               // 1184
constexpr int kSmemVec4  = kSmemFloats / 4;                     // 296
constexpr int kBlocksHalf = kHalfPixels / kPixPerBlock;         // 15360
}  // namespace

// Shared compute: loads + dot products + 8-lane reduction.
// Returns c1 vector in `a`; masked+scaled cost for this lane's l8 in ret.
__device__ __forceinline__ float cv_compute(const float4* __restrict__ c1,
                                            const float4* __restrict__ wr,
                                            int p, int l8, float4& a)
{
    const int w = p % kW;
    const int base4 = p * (kC / 4) + l8;

    const float m0 = (w >= 2)      ? (1.0f / 32.0f) : 0.0f;
    const float m1 = (w >= 1)      ? (1.0f / 32.0f) : 0.0f;
    const float m3 = (w < kW - 1)  ? (1.0f / 32.0f) : 0.0f;
    const float m4 = (w < kW - 2)  ? (1.0f / 32.0f) : 0.0f;

    const int o0 = (w >= 2)     ? -16 : 0;
    const int o1 = (w >= 1)     ?  -8 : 0;
    const int o3 = (w < kW - 1) ?   8 : 0;
    const int o4 = (w < kW - 2) ?  16 : 0;

    a               = __ldg(&c1[base4]);
    const float4 v0 = __ldg(&wr[base4 + o0]);
    const float4 v1 = __ldg(&wr[base4 + o1]);
    const float4 v2 = __ldg(&wr[base4]);
    const float4 v3 = __ldg(&wr[base4 + o3]);
    const float4 v4 = __ldg(&wr[base4 + o4]);

    float s0 = a.x * v0.x + a.y * v0.y + a.z * v0.z + a.w * v0.w;
    float s1 = a.x * v1.x + a.y * v1.y + a.z * v1.z + a.w * v1.w;
    float s2 = a.x * v2.x + a.y * v2.y + a.z * v2.z + a.w * v2.w;
    float s3 = a.x * v3.x + a.y * v3.y + a.z * v3.z + a.w * v3.w;
    float s4 = a.x * v4.x + a.y * v4.y + a.z * v4.z + a.w * v4.w;

#pragma unroll
    for (int sh = 4; sh > 0; sh >>= 1) {
        s0 += __shfl_xor_sync(0xffffffffu, s0, sh);
        s1 += __shfl_xor_sync(0xffffffffu, s1, sh);
        s2 += __shfl_xor_sync(0xffffffffu, s2, sh);
        s3 += __shfl_xor_sync(0xffffffffu, s3, sh);
        s4 += __shfl_xor_sync(0xffffffffu, s4, sh);
    }

    float v = s2 * (1.0f / 32.0f);       // center always valid
    if (l8 == 0) v = s0 * m0;
    else if (l8 == 1) v = s1 * m1;
    else if (l8 == 3) v = s3 * m3;
    else if (l8 == 4) v = s4 * m4;
    return v;
}

// ---- Variant A: smem-staged, fully coalesced STG.128 writeback -------------
__global__ __launch_bounds__(kThreads)
void cv_kernel_staged(const float4* __restrict__ c1,
                      const float4* __restrict__ wr,
                      float4* __restrict__ out)
{
    __shared__ float stage[kSmemFloats];

    const int warpInBlk = threadIdx.x >> 5;
    const int lane = threadIdx.x & 31;
    const int grp  = lane >> 3;
    const int l8   = lane & 7;

    const int pLocal = warpInBlk * kPixPerWarp + grp;
    const int p = blockIdx.x * kPixPerBlock + pLocal;   // pixels [0, kHalfPixels)

    float4 a;
    const float cost = cv_compute(c1, wr, p, l8, a);

    float* row = &stage[pLocal * kOutC];
    row[l8 * 4 + 0] = a.x;
    row[l8 * 4 + 1] = a.y;
    row[l8 * 4 + 2] = a.z;
    row[l8 * 4 + 3] = a.w;
    if (l8 < kOff) row[kC + l8] = cost;

    __syncthreads();

    const float4* sv = (const float4*)stage;
    float4* ob = out + (size_t)blockIdx.x * kSmemVec4;
    ob[threadIdx.x] = sv[threadIdx.x];
    if (threadIdx.x < kSmemVec4 - kThreads) {
        ob[kThreads + threadIdx.x] = sv[kThreads + threadIdx.x];
    }
}

// ---- Variant B: direct stores (R2 store path) ------------------------------
__global__ __launch_bounds__(kThreads)
void cv_kernel_direct(const float4* __restrict__ c1,
                      const float4* __restrict__ wr,
                      float* __restrict__ out)
{
    const int gwarp = (blockIdx.x * kThreads + threadIdx.x) >> 5;
    const int lane = threadIdx.x & 31;
    const int grp  = lane >> 3;
    const int l8   = lane & 7;

    const int p = kHalfPixels + gwarp * kPixPerWarp + grp;  // pixels [N/2, N)

    float4 a;
    const float cost = cv_compute(c1, wr, p, l8, a);

    const size_t obase = (size_t)p * kOutC;
    float* op = out + obase + l8 * 4;
    op[0] = a.x;
    op[1] = a.y;
    op[2] = a.z;
    op[3] = a.w;
    if (l8 < kOff) out[obase + kC + l8] = cost;
}

extern "C" void kernel_launch(void* const* d_in, const int* in_sizes, int n_in,
                              void* d_out, int out_size)
{
    const float4* c1 = (const float4*)d_in[0];
    const float4* wr = (const float4*)d_in[1];
    // d_in[2] is search_range (int32) — fixed at 2 for this problem's shapes.

    cv_kernel_staged<<<kBlocksHalf, kThreads>>>(c1, wr, (float4*)d_out);
    cv_kernel_direct<<<kBlocksHalf, kThreads>>>(c1, wr, (float*)d_out);
}